// round 1
// baseline (speedup 1.0000x reference)
#include <cuda_runtime.h>
#include <math.h>

#define BSZ   512
#define NFEAT 2048
#define OUTF  64
#define KD    16
#define MN    1024   // OUTF*KD
#define OUTW  2112   // NFEAT + OUTF

// scratch (no cudaMalloc allowed)
__device__ float g_m[BSZ * MN];       // m = x @ T   [512, 1024]
__device__ float g_acc[BSZ * OUTF];   // out accum   [512, 64]

__global__ void zero_acc_kernel() {
    int i = blockIdx.x * blockDim.x + threadIdx.x;
    if (i < BSZ * OUTF) g_acc[i] = 0.0f;
}

// ---------------- fp32 tiled GEMM: g_m = x @ T ----------------
#define BM 64
#define BN 64
#define BK 16
__global__ __launch_bounds__(256) void gemm_kernel(const float* __restrict__ x,
                                                   const float* __restrict__ T) {
    __shared__ float As[BK][BM];   // transposed stage: As[k][row]
    __shared__ float Bs[BK][BN];

    int bx = blockIdx.x;   // N tile (16)
    int by = blockIdx.y;   // M tile (8)
    int tid = threadIdx.x;
    int tx = tid % 16;     // 0..15 -> 4 cols each
    int ty = tid / 16;     // 0..15 -> 4 rows each

    int arow = tid / 4;            // 0..63
    int acol = (tid % 4) * 4;      // 0..12
    int brow = tid / 16;           // 0..15
    int bcol = (tid % 16) * 4;     // 0..60

    float acc[4][4] = {};

    for (int kt = 0; kt < NFEAT; kt += BK) {
        float4 av = *(const float4*)&x[(by * BM + arow) * NFEAT + kt + acol];
        As[acol + 0][arow] = av.x;
        As[acol + 1][arow] = av.y;
        As[acol + 2][arow] = av.z;
        As[acol + 3][arow] = av.w;
        float4 bv = *(const float4*)&T[(kt + brow) * MN + bx * BN + bcol];
        *(float4*)&Bs[brow][bcol] = bv;
        __syncthreads();

        #pragma unroll
        for (int k = 0; k < BK; k++) {
            float a[4], b[4];
            #pragma unroll
            for (int i = 0; i < 4; i++) a[i] = As[k][ty * 4 + i];
            #pragma unroll
            for (int j = 0; j < 4; j++) b[j] = Bs[k][tx * 4 + j];
            #pragma unroll
            for (int i = 0; i < 4; i++)
                #pragma unroll
                for (int j = 0; j < 4; j++)
                    acc[i][j] += a[i] * b[j];
        }
        __syncthreads();
    }

    #pragma unroll
    for (int i = 0; i < 4; i++)
        #pragma unroll
        for (int j = 0; j < 4; j++)
            g_m[(by * BM + ty * 4 + i) * MN + bx * BN + tx * 4 + j] = acc[i][j];
}

// ---------------- pairwise L1 + exp, partial sum over a j-chunk ----------------
#define JC 64   // j rows per block
__global__ __launch_bounds__(512) void pairwise_kernel() {
    int o  = blockIdx.x;        // feature 0..63
    int j0 = blockIdx.y * JC;   // j chunk base
    int tid = threadIdx.x;      // i row 0..511

    __shared__ float sj[JC][KD];

    // stage chunk rows: JC*KD = 1024 floats = 256 float4
    if (tid < 256) {
        int j  = tid / 4;
        int k4 = (tid % 4) * 4;
        *(float4*)&sj[j][k4] = *(const float4*)&g_m[(j0 + j) * MN + o * KD + k4];
    }

    // own row into registers (64B contiguous per thread)
    float mi[KD];
    #pragma unroll
    for (int k4 = 0; k4 < KD; k4 += 4) {
        float4 v = *(const float4*)&g_m[tid * MN + o * KD + k4];
        mi[k4 + 0] = v.x; mi[k4 + 1] = v.y; mi[k4 + 2] = v.z; mi[k4 + 3] = v.w;
    }
    __syncthreads();

    float acc = 0.0f;
    #pragma unroll 4
    for (int j = 0; j < JC; j++) {
        float d = 0.0f;
        #pragma unroll
        for (int k = 0; k < KD; k++) d += fabsf(mi[k] - sj[j][k]);
        acc += __expf(-d);
    }
    atomicAdd(&g_acc[tid * OUTF + o], acc);
}

// ---------------- finalize: out = concat([x, acc], axis=1) ----------------
__global__ __launch_bounds__(256) void finalize_kernel(const float* __restrict__ x,
                                                       float* __restrict__ out) {
    int row = blockIdx.x;
    int tid = threadIdx.x;
    const float4* xs = (const float4*)&x[row * NFEAT];
    float4* od = (float4*)&out[row * OUTW];   // 2112 floats/row -> 16B aligned
    #pragma unroll
    for (int i = tid; i < NFEAT / 4; i += 256) od[i] = xs[i];
    if (tid < OUTF / 4) {
        float4 v = *(const float4*)&g_acc[row * OUTF + tid * 4];
        od[NFEAT / 4 + tid] = v;
    }
}

extern "C" void kernel_launch(void* const* d_in, const int* in_sizes, int n_in,
                              void* d_out, int out_size) {
    const float* x = (const float*)d_in[0];
    const float* T = (const float*)d_in[1];
    float* out = (float*)d_out;

    zero_acc_kernel<<<(BSZ * OUTF + 255) / 256, 256>>>();
    gemm_kernel<<<dim3(MN / BN, BSZ / BM), 256>>>(x, T);
    pairwise_kernel<<<dim3(OUTF, BSZ / JC), 512>>>();
    finalize_kernel<<<BSZ, 256>>>(x, out);
}

// round 4
// speedup vs baseline: 2.1111x; 2.1111x over previous
#include <cuda_runtime.h>
#include <cuda_bf16.h>
#include <cstdint>
#include <math.h>

#define BSZ   512
#define NFEAT 2048
#define OUTF  64
#define KD    16
#define MN    1024   // OUTF*KD
#define OUTW  2112   // NFEAT + OUTF

// ---------------- scratch (no cudaMalloc allowed) ----------------
__device__ __align__(16) __nv_bfloat16 g_xb[BSZ * NFEAT];   // x bf16 [512,2048]
__device__ __align__(16) __nv_bfloat16 g_tb[MN * NFEAT];    // T^T bf16 [1024,2048] (K-major)
__device__ __align__(16) float g_m[BSZ * MN];               // m = x@T [512,1024]
__device__ __align__(16) float g_acc[BSZ * OUTF];           // out accum [512,64]

// ---------------- helpers ----------------
__device__ __forceinline__ uint32_t smem_u32(const void* p) {
    uint32_t a;
    asm("{ .reg .u64 t; cvta.to.shared.u64 t, %1; cvt.u32.u64 %0, t; }" : "=r"(a) : "l"(p));
    return a;
}
__device__ __forceinline__ void cp16(uint32_t dst, const void* src) {
    asm volatile("cp.async.cg.shared.global [%0], [%1], 16;" :: "r"(dst), "l"(src) : "memory");
}
__device__ __forceinline__ void cp_commit() {
    asm volatile("cp.async.commit_group;" ::: "memory");
}
__device__ __forceinline__ void ldsm_x4(uint32_t& r0, uint32_t& r1, uint32_t& r2, uint32_t& r3, uint32_t a) {
    asm volatile("ldmatrix.sync.aligned.m8n8.x4.shared.b16 {%0,%1,%2,%3}, [%4];"
                 : "=r"(r0), "=r"(r1), "=r"(r2), "=r"(r3) : "r"(a));
}
__device__ __forceinline__ void ldsm_x2(uint32_t& r0, uint32_t& r1, uint32_t a) {
    asm volatile("ldmatrix.sync.aligned.m8n8.x2.shared.b16 {%0,%1}, [%2];"
                 : "=r"(r0), "=r"(r1) : "r"(a));
}
__device__ __forceinline__ void mma16816(float* d, const uint32_t* a, const uint32_t* b) {
    asm volatile(
        "mma.sync.aligned.m16n8k16.row.col.f32.bf16.bf16.f32 "
        "{%0,%1,%2,%3}, {%4,%5,%6,%7}, {%8,%9}, {%0,%1,%2,%3};"
        : "+f"(d[0]), "+f"(d[1]), "+f"(d[2]), "+f"(d[3])
        : "r"(a[0]), "r"(a[1]), "r"(a[2]), "r"(a[3]), "r"(b[0]), "r"(b[1]));
}

// ---------------- conversion kernels ----------------
__global__ __launch_bounds__(256) void conv_x_kernel(const float* __restrict__ x) {
    int i = blockIdx.x * 256 + threadIdx.x;
    float4 v = ((const float4*)x)[i];
    __nv_bfloat162 a = __floats2bfloat162_rn(v.x, v.y);
    __nv_bfloat162 b = __floats2bfloat162_rn(v.z, v.w);
    uint2 o;
    o.x = *(uint32_t*)&a;
    o.y = *(uint32_t*)&b;
    ((uint2*)g_xb)[i] = o;
    if (i < (BSZ * OUTF) / 4) {
        float4 z = {0.f, 0.f, 0.f, 0.f};
        ((float4*)g_acc)[i] = z;
    }
}

// T [2048,1024] f32 -> g_tb [1024,2048] bf16 (transpose)
__global__ __launch_bounds__(256) void conv_T_kernel(const float* __restrict__ T) {
    __shared__ float tile[32][33];
    int n0 = blockIdx.x * 32;
    int k0 = blockIdx.y * 32;
    int tx = threadIdx.x, ty = threadIdx.y;
    #pragma unroll
    for (int i = 0; i < 4; i++)
        tile[ty + i * 8][tx] = T[(uint64_t)(k0 + ty + i * 8) * MN + n0 + tx];
    __syncthreads();
    #pragma unroll
    for (int i = 0; i < 4; i++)
        g_tb[(uint64_t)(n0 + ty + i * 8) * NFEAT + k0 + tx] = __float2bfloat16(tile[tx][ty + i * 8]);
}

// ---------------- bf16 mma.sync GEMM: g_m = x @ T  (M=512,N=1024,K=2048) ----------------
// CTA tile 64x64, 128 threads (4 warps, each 32x32), BK=32, double-buffered cp.async.
#define BK   32
#define ROWP 40            // padded row length (elems): banks 0,20,8,28,16,4,24,12 -> conflict-free
#define NSTG (NFEAT / BK)  // 64

__global__ __launch_bounds__(128) void gemm_mma_kernel() {
    __shared__ __nv_bfloat16 As[2][64 * ROWP];
    __shared__ __nv_bfloat16 Bs[2][64 * ROWP];

    int tid = threadIdx.x;
    int wid = tid >> 5, lane = tid & 31;
    int m0 = blockIdx.y * 64;
    int n0 = blockIdx.x * 64;
    int wm = (wid & 1) * 32;    // warp M offset
    int wn = (wid >> 1) * 32;   // warp N offset

    // cp.async mapping: 512 16B-chunks per stage (A 64x4 + B 64x4), 4 per thread
    uint32_t so[4];
    const __nv_bfloat16* gp[4];
    #pragma unroll
    for (int i = 0; i < 4; i++) {
        int chunk = i * 128 + tid;
        bool isB = chunk >= 256;
        int lc = chunk & 255;
        int r = lc >> 2;        // 0..63
        int c = lc & 3;         // 16B column
        so[i] = (uint32_t)(r * ROWP * 2 + c * 16);
        gp[i] = (isB ? g_tb + (uint64_t)(n0 + r) * NFEAT
                     : g_xb + (uint64_t)(m0 + r) * NFEAT) + c * 8;
    }
    uint32_t a_s0 = smem_u32(&As[0][0]);
    uint32_t b_s0 = smem_u32(&Bs[0][0]);

    auto load_stage = [&](int s, int buf) {
        #pragma unroll
        for (int i = 0; i < 4; i++) {
            uint32_t base = (i < 2) ? a_s0 : b_s0;
            cp16(base + buf * (64 * ROWP * 2) + so[i], gp[i] + s * BK);
        }
        cp_commit();
    };

    float acc[2][4][4] = {};

    load_stage(0, 0);

    for (int s = 0; s < NSTG; s++) {
        int buf = s & 1;
        if (s + 1 < NSTG) load_stage(s + 1, buf ^ 1);
        else              cp_commit();
        asm volatile("cp.async.wait_group 1;" ::: "memory");
        __syncthreads();

        uint32_t a_s = a_s0 + buf * (64 * ROWP * 2);
        uint32_t b_s = b_s0 + buf * (64 * ROWP * 2);

        #pragma unroll
        for (int ks = 0; ks < 2; ks++) {
            uint32_t af[2][4];
            #pragma unroll
            for (int mi = 0; mi < 2; mi++) {
                uint32_t addr = a_s + (uint32_t)(((wm + mi * 16 + (lane & 15)) * ROWP
                                      + ks * 16 + (lane >> 4) * 8) * 2);
                ldsm_x4(af[mi][0], af[mi][1], af[mi][2], af[mi][3], addr);
            }
            uint32_t bf[4][2];
            #pragma unroll
            for (int ni = 0; ni < 4; ni++) {
                uint32_t addr = b_s + (uint32_t)(((wn + ni * 8 + (lane & 7)) * ROWP
                                      + ks * 16 + ((lane >> 3) & 1) * 8) * 2);
                ldsm_x2(bf[ni][0], bf[ni][1], addr);
            }
            #pragma unroll
            for (int mi = 0; mi < 2; mi++)
                #pragma unroll
                for (int ni = 0; ni < 4; ni++)
                    mma16816(acc[mi][ni], af[mi], bf[ni]);
        }
        __syncthreads();
    }

    // epilogue: d0,d1 at (row, col..col+1); d2,d3 at (row+8)
    int row = lane >> 2;
    int col = (lane & 3) * 2;
    #pragma unroll
    for (int mi = 0; mi < 2; mi++) {
        #pragma unroll
        for (int ni = 0; ni < 4; ni++) {
            float* base = &g_m[(uint64_t)(m0 + wm + mi * 16 + row) * MN + n0 + wn + ni * 8 + col];
            float2 lo = {acc[mi][ni][0], acc[mi][ni][1]};
            float2 hi = {acc[mi][ni][2], acc[mi][ni][3]};
            *(float2*)base = lo;
            *(float2*)(base + 8 * MN) = hi;
        }
    }
}

// ---------------- pairwise L1 + exp (validated in R1) ----------------
#define JC 64
__global__ __launch_bounds__(512) void pairwise_kernel() {
    int o  = blockIdx.x;
    int j0 = blockIdx.y * JC;
    int tid = threadIdx.x;

    __shared__ float sj[JC][KD];

    if (tid < 256) {
        int j  = tid / 4;
        int k4 = (tid % 4) * 4;
        *(float4*)&sj[j][k4] = *(const float4*)&g_m[(uint64_t)(j0 + j) * MN + o * KD + k4];
    }

    float mi[KD];
    #pragma unroll
    for (int k4 = 0; k4 < KD; k4 += 4) {
        float4 v = *(const float4*)&g_m[(uint64_t)tid * MN + o * KD + k4];
        mi[k4 + 0] = v.x; mi[k4 + 1] = v.y; mi[k4 + 2] = v.z; mi[k4 + 3] = v.w;
    }
    __syncthreads();

    float acc = 0.0f;
    #pragma unroll 4
    for (int j = 0; j < JC; j++) {
        float d = 0.0f;
        #pragma unroll
        for (int k = 0; k < KD; k++) d += fabsf(mi[k] - sj[j][k]);
        acc += __expf(-d);
    }
    atomicAdd(&g_acc[tid * OUTF + o], acc);
}

// ---------------- finalize: out = concat([x, acc], axis=1) ----------------
__global__ __launch_bounds__(256) void finalize_kernel(const float* __restrict__ x,
                                                       float* __restrict__ out) {
    int i = blockIdx.x * 256 + threadIdx.x;
    int row = i / (OUTW / 4);
    int c4  = i % (OUTW / 4);
    float4 v;
    if (c4 < NFEAT / 4) v = ((const float4*)(x + (uint64_t)row * NFEAT))[c4];
    else                v = ((const float4*)(g_acc + (uint64_t)row * OUTF))[c4 - NFEAT / 4];
    ((float4*)(out + (uint64_t)row * OUTW))[c4] = v;
}

extern "C" void kernel_launch(void* const* d_in, const int* in_sizes, int n_in,
                              void* d_out, int out_size) {
    const float* x = (const float*)d_in[0];
    const float* T = (const float*)d_in[1];
    float* out = (float*)d_out;

    conv_x_kernel<<<(BSZ * NFEAT / 4) / 256, 256>>>(x);
    conv_T_kernel<<<dim3(MN / 32, NFEAT / 32), dim3(32, 8)>>>(T);
    gemm_mma_kernel<<<dim3(MN / 64, BSZ / 64), 128>>>();
    pairwise_kernel<<<dim3(OUTF, BSZ / JC), 512>>>();
    finalize_kernel<<<(BSZ * (OUTW / 4)) / 256, 256>>>(x, out);
}

// round 5
// speedup vs baseline: 2.6118x; 1.2372x over previous
#include <cuda_runtime.h>
#include <cuda_bf16.h>
#include <cstdint>
#include <math.h>

#define BSZ   512
#define NFEAT 2048
#define OUTF  64
#define KD    16
#define MN    1024   // OUTF*KD
#define OUTW  2112   // NFEAT + OUTF

// ---------------- scratch (no cudaMalloc allowed) ----------------
__device__ __align__(16) __nv_bfloat16 g_xb[BSZ * NFEAT];   // x bf16 [512,2048]
__device__ __align__(16) __nv_bfloat16 g_tb[MN * NFEAT];    // T^T bf16 [1024,2048] (K-major)
__device__ __align__(16) float g_m[BSZ * MN];               // m = x@T [512,1024]
__device__ __align__(16) float g_acc[BSZ * OUTF];           // out accum [512,64]

// ---------------- helpers ----------------
__device__ __forceinline__ uint32_t smem_u32(const void* p) {
    uint32_t a;
    asm("{ .reg .u64 t; cvta.to.shared.u64 t, %1; cvt.u32.u64 %0, t; }" : "=r"(a) : "l"(p));
    return a;
}
__device__ __forceinline__ void cp16(uint32_t dst, const void* src) {
    asm volatile("cp.async.cg.shared.global [%0], [%1], 16;" :: "r"(dst), "l"(src) : "memory");
}
__device__ __forceinline__ void cp_commit() {
    asm volatile("cp.async.commit_group;" ::: "memory");
}
__device__ __forceinline__ void ldsm_x4(uint32_t& r0, uint32_t& r1, uint32_t& r2, uint32_t& r3, uint32_t a) {
    asm volatile("ldmatrix.sync.aligned.m8n8.x4.shared.b16 {%0,%1,%2,%3}, [%4];"
                 : "=r"(r0), "=r"(r1), "=r"(r2), "=r"(r3) : "r"(a));
}
__device__ __forceinline__ void ldsm_x2(uint32_t& r0, uint32_t& r1, uint32_t a) {
    asm volatile("ldmatrix.sync.aligned.m8n8.x2.shared.b16 {%0,%1}, [%2];"
                 : "=r"(r0), "=r"(r1) : "r"(a));
}
__device__ __forceinline__ void mma16816(float* d, const uint32_t* a, const uint32_t* b) {
    asm volatile(
        "mma.sync.aligned.m16n8k16.row.col.f32.bf16.bf16.f32 "
        "{%0,%1,%2,%3}, {%4,%5,%6,%7}, {%8,%9}, {%0,%1,%2,%3};"
        : "+f"(d[0]), "+f"(d[1]), "+f"(d[2]), "+f"(d[3])
        : "r"(a[0]), "r"(a[1]), "r"(a[2]), "r"(a[3]), "r"(b[0]), "r"(b[1]));
}

// ---------------- conv_x: x f32 -> bf16 scratch, copy x -> out, zero g_acc ----------------
__global__ __launch_bounds__(256) void conv_x_kernel(const float* __restrict__ x,
                                                     float* __restrict__ out) {
    int i = blockIdx.x * 256 + threadIdx.x;       // over 262144 float4s
    float4 v = ((const float4*)x)[i];
    __nv_bfloat162 a = __floats2bfloat162_rn(v.x, v.y);
    __nv_bfloat162 b = __floats2bfloat162_rn(v.z, v.w);
    uint2 o;
    o.x = *(uint32_t*)&a;
    o.y = *(uint32_t*)&b;
    ((uint2*)g_xb)[i] = o;
    // copy x into the first 2048 columns of out
    int row = i >> 9;            // /512 float4s per x row
    int c4  = i & 511;
    ((float4*)(out + (uint64_t)row * OUTW))[c4] = v;
    if (i < (BSZ * OUTF) / 4) {
        float4 z = {0.f, 0.f, 0.f, 0.f};
        ((float4*)g_acc)[i] = z;
    }
}

// T [2048,1024] f32 -> g_tb [1024,2048] bf16 (transpose)
__global__ __launch_bounds__(256) void conv_T_kernel(const float* __restrict__ T) {
    __shared__ float tile[32][33];
    int n0 = blockIdx.x * 32;
    int k0 = blockIdx.y * 32;
    int tx = threadIdx.x, ty = threadIdx.y;
    #pragma unroll
    for (int i = 0; i < 4; i++)
        tile[ty + i * 8][tx] = T[(uint64_t)(k0 + ty + i * 8) * MN + n0 + tx];
    __syncthreads();
    #pragma unroll
    for (int i = 0; i < 4; i++)
        g_tb[(uint64_t)(n0 + ty + i * 8) * NFEAT + k0 + tx] = __float2bfloat16(tile[tx][ty + i * 8]);
}

// ---------------- bf16 mma.sync GEMM: g_m = x @ T  (M=512,N=1024,K=2048) ----------------
// CTA tile 64x64, 256 threads (8 warps, each 32x16), BK=32, double-buffered cp.async.
#define BK   32
#define ROWP 40            // padded row (elems) -> conflict-free ldmatrix
#define NSTG (NFEAT / BK)  // 64
#define STAGEB (64 * ROWP * 2)

__global__ __launch_bounds__(256) void gemm_mma_kernel() {
    __shared__ __nv_bfloat16 As[2][64 * ROWP];
    __shared__ __nv_bfloat16 Bs[2][64 * ROWP];

    int tid = threadIdx.x;
    int wid = tid >> 5, lane = tid & 31;
    int m0 = blockIdx.y * 64;
    int n0 = blockIdx.x * 64;
    int wm = (wid & 1) * 32;     // warp M offset (2 rows of warps)
    int wn = (wid >> 1) * 16;    // warp N offset (4 cols of warps)

    // cp.async mapping: 512 16B-chunks per stage (A 64x4 + B 64x4), 2 per thread
    uint32_t so[2];
    const __nv_bfloat16* gp[2];
    #pragma unroll
    for (int i = 0; i < 2; i++) {
        int lc = tid;            // 0..255 within each half
        int r = lc >> 2;         // 0..63
        int c = lc & 3;          // 16B column
        so[i] = (uint32_t)(r * ROWP * 2 + c * 16);
        gp[i] = (i ? g_tb + (uint64_t)(n0 + r) * NFEAT
                   : g_xb + (uint64_t)(m0 + r) * NFEAT) + c * 8;
    }
    uint32_t a_s0 = smem_u32(&As[0][0]);
    uint32_t b_s0 = smem_u32(&Bs[0][0]);

    auto load_stage = [&](int s, int buf) {
        cp16(a_s0 + buf * STAGEB + so[0], gp[0] + s * BK);
        cp16(b_s0 + buf * STAGEB + so[1], gp[1] + s * BK);
        cp_commit();
    };

    float acc[2][2][4] = {};

    load_stage(0, 0);

    for (int s = 0; s < NSTG; s++) {
        int buf = s & 1;
        if (s + 1 < NSTG) load_stage(s + 1, buf ^ 1);
        else              cp_commit();
        asm volatile("cp.async.wait_group 1;" ::: "memory");
        __syncthreads();

        uint32_t a_s = a_s0 + buf * STAGEB;
        uint32_t b_s = b_s0 + buf * STAGEB;

        #pragma unroll
        for (int ks = 0; ks < 2; ks++) {
            uint32_t af[2][4];
            #pragma unroll
            for (int mi = 0; mi < 2; mi++) {
                uint32_t addr = a_s + (uint32_t)(((wm + mi * 16 + (lane & 15)) * ROWP
                                      + ks * 16 + (lane >> 4) * 8) * 2);
                ldsm_x4(af[mi][0], af[mi][1], af[mi][2], af[mi][3], addr);
            }
            uint32_t bf[2][2];
            #pragma unroll
            for (int ni = 0; ni < 2; ni++) {
                uint32_t addr = b_s + (uint32_t)(((wn + ni * 8 + (lane & 7)) * ROWP
                                      + ks * 16 + ((lane >> 3) & 1) * 8) * 2);
                ldsm_x2(bf[ni][0], bf[ni][1], addr);
            }
            #pragma unroll
            for (int mi = 0; mi < 2; mi++)
                #pragma unroll
                for (int ni = 0; ni < 2; ni++)
                    mma16816(acc[mi][ni], af[mi], bf[ni]);
        }
        __syncthreads();
    }

    int row = lane >> 2;
    int col = (lane & 3) * 2;
    #pragma unroll
    for (int mi = 0; mi < 2; mi++) {
        #pragma unroll
        for (int ni = 0; ni < 2; ni++) {
            float* base = &g_m[(uint64_t)(m0 + wm + mi * 16 + row) * MN + n0 + wn + ni * 8 + col];
            float2 lo = {acc[mi][ni][0], acc[mi][ni][1]};
            float2 hi = {acc[mi][ni][2], acc[mi][ni][3]};
            *(float2*)base = lo;
            *(float2*)(base + 8 * MN) = hi;
        }
    }
}

// ---------------- pairwise L1 + exp with early exit ----------------
// d >= d4 (first 4 |diffs|); if d4 >= 44, contribution <= e^-44*511 ~ 4e-17 << 1e-3*out.
#define JC 64
#define CUTOFF 44.0f
__global__ __launch_bounds__(512) void pairwise_kernel() {
    int o  = blockIdx.x;
    int j0 = blockIdx.y * JC;
    int tid = threadIdx.x;

    __shared__ float4 sj4[JC][4];

    if (tid < 256) {
        int j = tid >> 2;
        int q = tid & 3;
        sj4[j][q] = *(const float4*)&g_m[(uint64_t)(j0 + j) * MN + o * KD + q * 4];
    }

    const float* mrow = &g_m[(uint64_t)tid * MN + o * KD];
    float4 m0 = *(const float4*)(mrow + 0);
    float4 m1 = *(const float4*)(mrow + 4);
    float4 m2 = *(const float4*)(mrow + 8);
    float4 m3 = *(const float4*)(mrow + 12);
    __syncthreads();

    float acc = 0.0f;
    #pragma unroll 4
    for (int j = 0; j < JC; j++) {
        float4 v0 = sj4[j][0];
        float d4 = fabsf(m0.x - v0.x) + fabsf(m0.y - v0.y)
                 + fabsf(m0.z - v0.z) + fabsf(m0.w - v0.w);
        if (d4 < CUTOFF) {
            float4 v1 = sj4[j][1];
            float4 v2 = sj4[j][2];
            float4 v3 = sj4[j][3];
            float d = d4
                + fabsf(m1.x - v1.x) + fabsf(m1.y - v1.y) + fabsf(m1.z - v1.z) + fabsf(m1.w - v1.w)
                + fabsf(m2.x - v2.x) + fabsf(m2.y - v2.y) + fabsf(m2.z - v2.z) + fabsf(m2.w - v2.w)
                + fabsf(m3.x - v3.x) + fabsf(m3.y - v3.y) + fabsf(m3.z - v3.z) + fabsf(m3.w - v3.w);
            acc += __expf(-d);
        }
    }
    atomicAdd(&g_acc[tid * OUTF + o], acc);
}

// ---------------- finalize: write only the 64 appended columns ----------------
__global__ __launch_bounds__(256) void finalize_kernel(float* __restrict__ out) {
    int i = blockIdx.x * 256 + threadIdx.x;   // over 512*16 float4s
    int row = i >> 4;
    int c4  = i & 15;
    float4 v = ((const float4*)(g_acc + (uint64_t)row * OUTF))[c4];
    ((float4*)(out + (uint64_t)row * OUTW + NFEAT))[c4] = v;
}

extern "C" void kernel_launch(void* const* d_in, const int* in_sizes, int n_in,
                              void* d_out, int out_size) {
    const float* x = (const float*)d_in[0];
    const float* T = (const float*)d_in[1];
    float* out = (float*)d_out;

    conv_x_kernel<<<(BSZ * NFEAT / 4) / 256, 256>>>(x, out);
    conv_T_kernel<<<dim3(MN / 32, NFEAT / 32), dim3(32, 8)>>>(T);
    gemm_mma_kernel<<<dim3(MN / 64, BSZ / 64), 256>>>();
    pairwise_kernel<<<dim3(OUTF, BSZ / JC), 512>>>();
    finalize_kernel<<<(BSZ * (OUTF / 4)) / 256, 256>>>(out);
}

// round 6
// speedup vs baseline: 3.8432x; 1.4714x over previous
#include <cuda_runtime.h>
#include <cuda_bf16.h>
#include <cstdint>
#include <math.h>

#define BSZ   512
#define NFEAT 2048
#define OUTF  64
#define KD    16
#define MN    1024   // OUTF*KD
#define OUTW  2112   // NFEAT + OUTF

// ---------------- scratch (no cudaMalloc allowed) ----------------
__device__ __align__(16) __nv_bfloat16 g_xb[BSZ * NFEAT];   // x bf16 [512,2048]
__device__ __align__(16) __nv_bfloat16 g_tb[MN * NFEAT];    // T^T bf16 [1024,2048] (K-major)
__device__ __align__(16) float g_m[BSZ * MN];               // m = x@T [512,1024]
__device__ __align__(16) float g_acc[BSZ * OUTF];           // out accum [512,64]

// ---------------- helpers ----------------
__device__ __forceinline__ uint32_t smem_u32(const void* p) {
    uint32_t a;
    asm("{ .reg .u64 t; cvta.to.shared.u64 t, %1; cvt.u32.u64 %0, t; }" : "=r"(a) : "l"(p));
    return a;
}
__device__ __forceinline__ void cp16(uint32_t dst, const void* src) {
    asm volatile("cp.async.cg.shared.global [%0], [%1], 16;" :: "r"(dst), "l"(src) : "memory");
}
__device__ __forceinline__ void cp_commit() {
    asm volatile("cp.async.commit_group;" ::: "memory");
}
__device__ __forceinline__ void ldsm_x4(uint32_t& r0, uint32_t& r1, uint32_t& r2, uint32_t& r3, uint32_t a) {
    asm volatile("ldmatrix.sync.aligned.m8n8.x4.shared.b16 {%0,%1,%2,%3}, [%4];"
                 : "=r"(r0), "=r"(r1), "=r"(r2), "=r"(r3) : "r"(a));
}
__device__ __forceinline__ void ldsm_x2(uint32_t& r0, uint32_t& r1, uint32_t a) {
    asm volatile("ldmatrix.sync.aligned.m8n8.x2.shared.b16 {%0,%1}, [%2];"
                 : "=r"(r0), "=r"(r1) : "r"(a));
}
__device__ __forceinline__ void mma16816(float* d, const uint32_t* a, const uint32_t* b) {
    asm volatile(
        "mma.sync.aligned.m16n8k16.row.col.f32.bf16.bf16.f32 "
        "{%0,%1,%2,%3}, {%4,%5,%6,%7}, {%8,%9}, {%0,%1,%2,%3};"
        : "+f"(d[0]), "+f"(d[1]), "+f"(d[2]), "+f"(d[3])
        : "r"(a[0]), "r"(a[1]), "r"(a[2]), "r"(a[3]), "r"(b[0]), "r"(b[1]));
}
__device__ __forceinline__ uint32_t sw128(uint32_t off) { return off ^ ((off >> 3) & 0x70); }

// ---------------- merged conversions: x->bf16 (+out copy, acc=1.0), T->T^T bf16 ----------------
__global__ __launch_bounds__(256) void conv_kernel(const float* __restrict__ x,
                                                   const float* __restrict__ T,
                                                   float* __restrict__ out) {
    __shared__ float tile[32][33];
    int b = blockIdx.x;
    int tid = threadIdx.x;
    if (b < 1024) {
        int i = b * 256 + tid;                    // over 262144 float4s of x
        float4 v = ((const float4*)x)[i];
        __nv_bfloat162 a = __floats2bfloat162_rn(v.x, v.y);
        __nv_bfloat162 c = __floats2bfloat162_rn(v.z, v.w);
        uint2 o;
        o.x = *(uint32_t*)&a;
        o.y = *(uint32_t*)&c;
        ((uint2*)g_xb)[i] = o;
        int row = i >> 9;
        int c4  = i & 511;
        ((float4*)(out + (uint64_t)row * OUTW))[c4] = v;
        if (i < (BSZ * OUTF) / 4) {
            float4 one = {1.f, 1.f, 1.f, 1.f};    // self term exp(0)=1
            ((float4*)g_acc)[i] = one;
        }
    } else {
        int bb = b - 1024;                        // 0..2047: transpose T 32x32 tiles
        int n0 = (bb & 31) * 32;
        int k0 = (bb >> 5) * 32;
        int tx = tid & 31, ty = tid >> 5;         // (32,8)
        #pragma unroll
        for (int i = 0; i < 4; i++)
            tile[ty + i * 8][tx] = T[(uint64_t)(k0 + ty + i * 8) * MN + n0 + tx];
        __syncthreads();
        #pragma unroll
        for (int i = 0; i < 4; i++)
            g_tb[(uint64_t)(n0 + ty + i * 8) * NFEAT + k0 + tx] = __float2bfloat16(tile[tx][ty + i * 8]);
    }
}

// ---------------- bf16 mma.sync GEMM: g_m = x @ T  (M=512,N=1024,K=2048) ----------------
// CTA 64x64, 256 thr (8 warps, 32x16 each), BK=64, SW128 smem, 3-buffer ring, 1 sync/stage.
#define BK   64
#define NSTG (NFEAT / BK)      // 32
#define OPB  8192              // one operand tile: 64 rows x 128B
#define STAGEB 16384           // A + B per buffer

__global__ __launch_bounds__(256) void gemm_mma_kernel() {
    __shared__ __align__(1024) char gsm[3 * STAGEB];   // 48KB exactly

    int tid = threadIdx.x;
    int wid = tid >> 5, lane = tid & 31;
    int m0 = blockIdx.y * 64;
    int n0 = blockIdx.x * 64;
    int wm = (wid & 1) * 32;
    int wn = (wid >> 1) * 16;
    uint32_t sb = smem_u32(gsm);

    // cp.async mapping: 1024 16B-chunks/stage (A 64x8 + B 64x8), 4 per thread
    uint32_t so[4];
    const __nv_bfloat16* gp[4];
    #pragma unroll
    for (int i = 0; i < 4; i++) {
        int chunk = i * 256 + tid;
        bool isB = chunk >= 512;
        int lc = chunk & 511;
        int r = lc >> 3;        // 0..63
        int c = lc & 7;         // 16B col in 128B row
        so[i] = sw128((uint32_t)(r * 128 + c * 16)) + (isB ? OPB : 0u);
        gp[i] = (isB ? g_tb + (uint64_t)(n0 + r) * NFEAT
                     : g_xb + (uint64_t)(m0 + r) * NFEAT) + c * 8;
    }

    auto load_stage = [&](int s, int buf) {
        uint32_t base = sb + buf * STAGEB;
        #pragma unroll
        for (int i = 0; i < 4; i++) cp16(base + so[i], gp[i] + s * BK);
        cp_commit();
    };

    float acc[2][2][4] = {};

    load_stage(0, 0);
    load_stage(1, 1);

    for (int s = 0; s < NSTG; s++) {
        asm volatile("cp.async.wait_group 1;" ::: "memory");
        __syncthreads();
        if (s + 2 < NSTG) load_stage(s + 2, (s + 2) % 3);
        else              cp_commit();

        uint32_t a_b = sb + (s % 3) * STAGEB;
        uint32_t b_b = a_b + OPB;

        #pragma unroll
        for (int ks = 0; ks < 4; ks++) {
            uint32_t af[2][4];
            #pragma unroll
            for (int mi = 0; mi < 2; mi++) {
                uint32_t off = (uint32_t)((wm + mi * 16 + (lane & 15)) * 128
                                          + ks * 32 + (lane >> 4) * 16);
                ldsm_x4(af[mi][0], af[mi][1], af[mi][2], af[mi][3], a_b + sw128(off));
            }
            uint32_t bf[2][2];
            #pragma unroll
            for (int ni = 0; ni < 2; ni++) {
                uint32_t off = (uint32_t)((wn + ni * 8 + (lane & 7)) * 128
                                          + ks * 32 + ((lane >> 3) & 1) * 16);
                ldsm_x2(bf[ni][0], bf[ni][1], b_b + sw128(off));
            }
            #pragma unroll
            for (int mi = 0; mi < 2; mi++)
                #pragma unroll
                for (int ni = 0; ni < 2; ni++)
                    mma16816(acc[mi][ni], af[mi], bf[ni]);
        }
    }

    int row = lane >> 2;
    int col = (lane & 3) * 2;
    #pragma unroll
    for (int mi = 0; mi < 2; mi++) {
        #pragma unroll
        for (int ni = 0; ni < 2; ni++) {
            float* base = &g_m[(uint64_t)(m0 + wm + mi * 16 + row) * MN + n0 + wn + ni * 8 + col];
            float2 lo = {acc[mi][ni][0], acc[mi][ni][1]};
            float2 hi = {acc[mi][ni][2], acc[mi][ni][3]};
            *(float2*)base = lo;
            *(float2*)(base + 8 * MN) = hi;
        }
    }
}

// ---------------- symmetric pairwise L1 + exp with early exit ----------------
// Triangular 64x64 tile pairs; each surviving pair adds e to both rows' accumulators.
#define CUTOFF 44.0f
__global__ __launch_bounds__(256) void pairwise_kernel() {
    // decode blockIdx.x (0..35) -> (ti, tj), ti <= tj
    int p = blockIdx.x;
    int ti = 0, rowlen = 8;
    while (p >= rowlen) { p -= rowlen; rowlen--; ti++; }
    int tj = ti + p;
    int o = blockIdx.y;
    int i0 = ti * 64, j0 = tj * 64;
    bool diag = (ti == tj);

    __shared__ float4 smi[64][4];
    __shared__ float4 smj[64][4];
    __shared__ float sacc_i[64], sacc_j[64];

    int tid = threadIdx.x;
    {
        int r = tid >> 2, q = tid & 3;
        smi[r][q] = *(const float4*)&g_m[(uint64_t)(i0 + r) * MN + o * KD + q * 4];
        smj[r][q] = *(const float4*)&g_m[(uint64_t)(j0 + r) * MN + o * KD + q * 4];
    }
    if (tid < 64) { sacc_i[tid] = 0.f; sacc_j[tid] = 0.f; }
    __syncthreads();

    int il = tid & 63;
    int jc = tid >> 6;          // 4 chunks of 16 j
    float4 m0 = smi[il][0], m1 = smi[il][1], m2 = smi[il][2], m3 = smi[il][3];

    float accI = 0.f;
    #pragma unroll 4
    for (int j = jc * 16; j < jc * 16 + 16; j++) {
        if (diag && j <= il) continue;           // strict upper triangle on diagonal tiles
        float4 v0 = smj[j][0];
        float d4 = fabsf(m0.x - v0.x) + fabsf(m0.y - v0.y)
                 + fabsf(m0.z - v0.z) + fabsf(m0.w - v0.w);
        if (d4 < CUTOFF) {
            float4 v1 = smj[j][1];
            float4 v2 = smj[j][2];
            float4 v3 = smj[j][3];
            float d = d4
                + fabsf(m1.x - v1.x) + fabsf(m1.y - v1.y) + fabsf(m1.z - v1.z) + fabsf(m1.w - v1.w)
                + fabsf(m2.x - v2.x) + fabsf(m2.y - v2.y) + fabsf(m2.z - v2.z) + fabsf(m2.w - v2.w)
                + fabsf(m3.x - v3.x) + fabsf(m3.y - v3.y) + fabsf(m3.z - v3.z) + fabsf(m3.w - v3.w);
            float e = __expf(-d);
            accI += e;
            atomicAdd(&sacc_j[j], e);
        }
    }
    if (accI != 0.f) atomicAdd(&sacc_i[il], accI);
    __syncthreads();

    if (tid < 64) {
        float v = sacc_i[tid];
        if (v != 0.f) atomicAdd(&g_acc[(uint64_t)(i0 + tid) * OUTF + o], v);
    } else if (tid < 128) {
        int t = tid - 64;
        float v = sacc_j[t];
        if (v != 0.f) atomicAdd(&g_acc[(uint64_t)(j0 + t) * OUTF + o], v);
    }
}

// ---------------- finalize: write the 64 appended columns ----------------
__global__ __launch_bounds__(256) void finalize_kernel(float* __restrict__ out) {
    int i = blockIdx.x * 256 + threadIdx.x;   // over 512*16 float4s
    int row = i >> 4;
    int c4  = i & 15;
    float4 v = ((const float4*)(g_acc + (uint64_t)row * OUTF))[c4];
    ((float4*)(out + (uint64_t)row * OUTW + NFEAT))[c4] = v;
}

extern "C" void kernel_launch(void* const* d_in, const int* in_sizes, int n_in,
                              void* d_out, int out_size) {
    const float* x = (const float*)d_in[0];
    const float* T = (const float*)d_in[1];
    float* out = (float*)d_out;

    conv_kernel<<<3072, 256>>>(x, T, out);
    gemm_mma_kernel<<<dim3(MN / 64, BSZ / 64), 256>>>();
    pairwise_kernel<<<dim3(36, 64), 256>>>();
    finalize_kernel<<<(BSZ * (OUTF / 4)) / 256, 256>>>(out);
}